// round 17
// baseline (speedup 1.0000x reference)
#include <cuda_runtime.h>
#include <cuda_bf16.h>
#include <cstdint>

#define NNODES 200000
#define NEDGES 600000
#define NCH    128
#define SK     136            // padded bf16 row stride
#define SKB    (SK * 2)
#define CHUNK  512
#define NCHUNK ((NNODES + CHUNK - 1) / CHUNK)   // 391
#define MMA_GRID 152
#define MMA_THREADS 384       // 8 consumer warps + 4 producer warps

// ---------------- scratch ----------------
__device__ float g_h[(size_t)NNODES * NCH];
__device__ float g_acc[(size_t)NNODES * NCH];
__device__ float g_dinv[NNODES];
__device__ int   g_indeg[NNODES];
__device__ int   g_cursor[NNODES];
__device__ int   g_rowptr[NNODES];
__device__ int   g_bsum[CHUNK];
__device__ int   g_bbase[CHUNK];
__device__ int   g_esrc[NEDGES];
__device__ float g_sum[NCH];
__device__ float g_sumsq[NCH];
__device__ float g_scale[NCH];
__device__ float g_shift[NCH];
__device__ __nv_bfloat16 g_Wt[4][NCH * NCH];   // W1hi W1lo W2hi W2lo, [n][k]

// ---------------- prep ----------------
__global__ void k_convW(const float* __restrict__ W1, const float* __restrict__ W2, int n) {
    int idx = blockIdx.x * blockDim.x + threadIdx.x;
    if (idx < NCH) { g_sum[idx] = 0.f; g_sumsq[idx] = 0.f; }
    if (idx < n) { g_indeg[idx] = 0; g_cursor[idx] = 0; }
    if (idx >= NCH * NCH) return;
    int nn = idx & 127, kk = idx >> 7;
    int o = nn * NCH + kk;
    float v1 = W1[idx], v2 = W2[idx];
    __nv_bfloat16 h1 = __float2bfloat16(v1);
    __nv_bfloat16 h2 = __float2bfloat16(v2);
    g_Wt[0][o] = h1; g_Wt[1][o] = __float2bfloat16(v1 - __bfloat162float(h1));
    g_Wt[2][o] = h2; g_Wt[3][o] = __float2bfloat16(v2 - __bfloat162float(h2));
}

__global__ void k_stats(const float* __restrict__ x, const float* __restrict__ aP, int n) {
    __shared__ float4 rs[8][32];
    __shared__ float4 rq[8][32];
    int tid = threadIdx.x, c4 = tid & 31, ry = tid >> 5;
    float av = aP[0];
    float4 s = make_float4(0, 0, 0, 0), q = make_float4(0, 0, 0, 0);
    for (int base = blockIdx.x * 32; base < n; base += gridDim.x * 32) {
#pragma unroll
        for (int u = 0; u < 4; u++) {
            int r = base + ry + u * 8;
            if (r < n) {
                float4 v = ((const float4*)x)[(size_t)r * 32 + c4];
                v.x = v.x >= 0.f ? v.x : av * v.x;
                v.y = v.y >= 0.f ? v.y : av * v.y;
                v.z = v.z >= 0.f ? v.z : av * v.z;
                v.w = v.w >= 0.f ? v.w : av * v.w;
                s.x += v.x; s.y += v.y; s.z += v.z; s.w += v.w;
                q.x += v.x * v.x; q.y += v.y * v.y; q.z += v.z * v.z; q.w += v.w * v.w;
            }
        }
    }
    rs[ry][c4] = s; rq[ry][c4] = q;
    __syncthreads();
    if (ry == 0) {
        float4 S = rs[0][c4], Q = rq[0][c4];
#pragma unroll
        for (int i = 1; i < 8; i++) {
            float4 a = rs[i][c4], b = rq[i][c4];
            S.x += a.x; S.y += a.y; S.z += a.z; S.w += a.w;
            Q.x += b.x; Q.y += b.y; Q.z += b.z; Q.w += b.w;
        }
        atomicAdd(&g_sum[c4 * 4 + 0], S.x); atomicAdd(&g_sum[c4 * 4 + 1], S.y);
        atomicAdd(&g_sum[c4 * 4 + 2], S.z); atomicAdd(&g_sum[c4 * 4 + 3], S.w);
        atomicAdd(&g_sumsq[c4 * 4 + 0], Q.x); atomicAdd(&g_sumsq[c4 * 4 + 1], Q.y);
        atomicAdd(&g_sumsq[c4 * 4 + 2], Q.z); atomicAdd(&g_sumsq[c4 * 4 + 3], Q.w);
    }
}

__global__ void k_finalize(const float* __restrict__ gamma, const float* __restrict__ beta, int n) {
    int c = threadIdx.x;
    if (c >= NCH) return;
    float invn = 1.0f / (float)n;
    float mean = g_sum[c] * invn;
    float var  = g_sumsq[c] * invn - mean * mean;
    float sc   = gamma[c] * rsqrtf(var + 1e-5f);
    g_scale[c] = sc;
    g_shift[c] = beta[c] - mean * sc;
}

__global__ void k_count(const int* __restrict__ dst, int e) {
    int i = blockIdx.x * blockDim.x + threadIdx.x;
    if (i < e) atomicAdd(&g_indeg[dst[i]], 1);
}

__global__ void k_scan1(int n) {
    __shared__ int sh[CHUNK];
    int i = blockIdx.x * CHUNK + threadIdx.x;
    sh[threadIdx.x] = (i < n) ? g_indeg[i] : 0;
    __syncthreads();
    for (int s = CHUNK / 2; s > 0; s >>= 1) {
        if (threadIdx.x < s) sh[threadIdx.x] += sh[threadIdx.x + s];
        __syncthreads();
    }
    if (threadIdx.x == 0) g_bsum[blockIdx.x] = sh[0];
}
__global__ void k_scan2() {
    __shared__ int sh[CHUNK];
    int t = threadIdx.x;
    sh[t] = (t < NCHUNK) ? g_bsum[t] : 0;
    __syncthreads();
    for (int d = 1; d < CHUNK; d <<= 1) {
        int v = (t >= d) ? sh[t - d] : 0;
        __syncthreads();
        sh[t] += v;
        __syncthreads();
    }
    if (t < NCHUNK) g_bbase[t] = (t == 0) ? 0 : sh[t - 1];
}
__global__ void k_scan3(int n) {
    __shared__ int sh[CHUNK];
    int t = threadIdx.x;
    int i = blockIdx.x * CHUNK + t;
    int v0 = (i < n) ? g_indeg[i] : 0;
    sh[t] = v0;
    __syncthreads();
    for (int d = 1; d < CHUNK; d <<= 1) {
        int v = (t >= d) ? sh[t - d] : 0;
        __syncthreads();
        sh[t] += v;
        __syncthreads();
    }
    if (i < n) {
        g_rowptr[i] = g_bbase[blockIdx.x] + sh[t] - v0;
        g_dinv[i] = rsqrtf((float)(v0 + 1));
    }
}
__global__ void k_fill(const int* __restrict__ src, const int* __restrict__ dst, int e) {
    int i = blockIdx.x * blockDim.x + threadIdx.x;
    if (i >= e) return;
    int d = dst[i];
    int pos = g_rowptr[d] + atomicAdd(&g_cursor[d], 1);
    g_esrc[pos] = src[i];
}

// ---------------- HMMA / barrier helpers ----------------
__device__ __forceinline__ void mma16816(float* c, const uint32_t* a, const uint32_t* b) {
    asm volatile(
        "mma.sync.aligned.m16n8k16.row.col.f32.bf16.bf16.f32 "
        "{%0,%1,%2,%3}, {%4,%5,%6,%7}, {%8,%9}, {%0,%1,%2,%3};"
        : "+f"(c[0]), "+f"(c[1]), "+f"(c[2]), "+f"(c[3])
        : "r"(a[0]), "r"(a[1]), "r"(a[2]), "r"(a[3]), "r"(b[0]), "r"(b[1]));
}
__device__ __forceinline__ void ldsm4(uint32_t* r, uint32_t addr) {
    asm volatile("ldmatrix.sync.aligned.m8n8.x4.shared.b16 {%0,%1,%2,%3}, [%4];"
                 : "=r"(r[0]), "=r"(r[1]), "=r"(r[2]), "=r"(r[3]) : "r"(addr));
}
__device__ __forceinline__ uint32_t pack_bf2(float x, float y) {
    __nv_bfloat162 h = __floats2bfloat162_rn(x, y);
    return *(uint32_t*)&h;
}
#define BARS(id) asm volatile("bar.sync %0, %1;"   :: "r"(id), "n"(MMA_THREADS) : "memory")
#define BARA(id) asm volatile("bar.arrive %0, %1;" :: "r"(id), "n"(MMA_THREADS) : "memory")

// ---------------- warp-specialized persistent GEMM ----------------
// warps 0-7: compute (ldsm+mma+stg). warps 8-11: produce (LDG f32, transform, split, STS).
// Double-buffered AH/AL; named-barrier full/empty handshake.
template <int MODE>
__global__ void __launch_bounds__(MMA_THREADS)
k_mma(const float* __restrict__ Ain,
      const __nv_bfloat16* __restrict__ Whi, const __nv_bfloat16* __restrict__ Wlo,
      const float* __restrict__ aP, int n, int ntiles)
{
    extern __shared__ char sm[];
    const int ABUFSZ = 2 * 128 * SKB;             // AH + AL per buffer
    const int WH = 2 * ABUFSZ, WL = WH + 128 * SKB;
    int tid = threadIdx.x;
    uint32_t sbase = (uint32_t)__cvta_generic_to_shared(sm);

    // ---- W splits: all threads, once ----
    {
        const uint4* wh4 = (const uint4*)Whi;
        const uint4* wl4 = (const uint4*)Wlo;
        for (int idx = tid; idx < 2048; idx += MMA_THREADS) {
            int rw = idx >> 4, cm = idx & 15;
            *(uint4*)(sm + WH + rw * SKB + cm * 16) = wh4[idx];
            *(uint4*)(sm + WL + rw * SKB + cm * 16) = wl4[idx];
        }
    }
    __syncthreads();

    if (tid >= 256) {
        // ================= producer =================
        int ptid = tid - 256;          // 0..127
        int colg = ptid & 31;          // float4 column group
        int rbase = ptid >> 2;         // row phase — recomputed below properly
        rbase = ptid >> 5;             // 0..3 (warp within producers)
        float av = aP[0];
        float4 sc, sf;
        if (MODE == 0) {
            sc = ((const float4*)g_scale)[colg];
            sf = ((const float4*)g_shift)[colg];
        }
        int it = 0;
        for (int t = blockIdx.x; t < ntiles; t += gridDim.x, it++) {
            int p = it & 1;
            if (it >= 2) BARS(3 + p);          // wait buffer p empty
            char* bufh = sm + p * ABUFSZ;
            char* bufl = bufh + 128 * SKB;
#pragma unroll 4
            for (int k = 0; k < 32; k++) {
                int rr = rbase + k * 4;        // rows: coalesced 4-row groups
                int r = t * 128 + rr;
                float4 v = make_float4(0.f, 0.f, 0.f, 0.f);
                if (r < n) v = __ldg(((const float4*)(Ain + (size_t)r * NCH)) + colg);
                v.x = v.x >= 0.f ? v.x : av * v.x;
                v.y = v.y >= 0.f ? v.y : av * v.y;
                v.z = v.z >= 0.f ? v.z : av * v.z;
                v.w = v.w >= 0.f ? v.w : av * v.w;
                if (MODE == 0) {
                    v.x = fmaf(v.x, sc.x, sf.x); v.y = fmaf(v.y, sc.y, sf.y);
                    v.z = fmaf(v.z, sc.z, sf.z); v.w = fmaf(v.w, sc.w, sf.w);
                }
                __nv_bfloat16 hx = __float2bfloat16(v.x), hy = __float2bfloat16(v.y);
                __nv_bfloat16 hz = __float2bfloat16(v.z), hw = __float2bfloat16(v.w);
                uint2 hi; hi.x = pack_bf2(v.x, v.y); hi.y = pack_bf2(v.z, v.w);
                float lx = v.x - __bfloat162float(hx), ly = v.y - __bfloat162float(hy);
                float lz = v.z - __bfloat162float(hz), lw = v.w - __bfloat162float(hw);
                uint2 lo; lo.x = pack_bf2(lx, ly); lo.y = pack_bf2(lz, lw);
                *(uint2*)(bufh + rr * SKB + colg * 8) = hi;
                *(uint2*)(bufl + rr * SKB + colg * 8) = lo;
            }
            BARA(1 + p);                       // buffer p full
        }
    } else {
        // ================= consumer =================
        int warp = tid >> 5, lane = tid & 31;
        int g = lane >> 2, tg = lane & 3;
        int m0 = (warp & 3) * 32;
        int n0 = (warp >> 2) * 64;
        int sel = lane >> 3, rowin = lane & 7;
        uint32_t aoffA = (uint32_t)((m0 + (sel & 1) * 8 + rowin) * SKB + (sel >> 1) * 16);
        uint32_t boffB = (uint32_t)((n0 + (sel >> 1) * 8 + rowin) * SKB + (sel & 1) * 16);

        int it = 0;
        for (int t = blockIdx.x; t < ntiles; t += gridDim.x, it++) {
            int p = it & 1;
            BARS(1 + p);                       // wait buffer p full
            uint32_t abh = sbase + p * ABUFSZ;
            uint32_t abl = abh + 128 * SKB;

            float acc[2][8][4];
#pragma unroll
            for (int mt = 0; mt < 2; mt++)
#pragma unroll
                for (int j = 0; j < 8; j++)
#pragma unroll
                    for (int v = 0; v < 4; v++) acc[mt][j][v] = 0.f;

#pragma unroll
            for (int kc = 0; kc < 8; kc++) {
                uint32_t kb = kc * 32;
                uint32_t ah[2][4], al[2][4];
#pragma unroll
                for (int mt = 0; mt < 2; mt++) {
                    ldsm4(ah[mt], abh + aoffA + mt * (16 * SKB) + kb);
                    ldsm4(al[mt], abl + aoffA + mt * (16 * SKB) + kb);
                }
#pragma unroll
                for (int jp = 0; jp < 4; jp++) {
                    uint32_t bh[4], bl[4];
                    ldsm4(bh, sbase + WH + boffB + jp * (16 * SKB) + kb);
                    ldsm4(bl, sbase + WL + boffB + jp * (16 * SKB) + kb);
#pragma unroll
                    for (int hf = 0; hf < 2; hf++) {
                        int j = jp * 2 + hf;
#pragma unroll
                        for (int mt = 0; mt < 2; mt++) {
                            mma16816(acc[mt][j], ah[mt], bh + hf * 2);
                            mma16816(acc[mt][j], ah[mt], bl + hf * 2);
                            mma16816(acc[mt][j], al[mt], bh + hf * 2);
                        }
                    }
                }
            }
            BARA(3 + p);                       // buffer p empty (fragments in regs)

            int row0 = t * 128;
#pragma unroll
            for (int mt = 0; mt < 2; mt++) {
                int rA = row0 + m0 + mt * 16 + g;
                int rB = rA + 8;
#pragma unroll
                for (int j = 0; j < 8; j++) {
                    int col = n0 + j * 8 + 2 * tg;
                    if (rA < n)
                        *(float2*)(g_h + (size_t)rA * NCH + col) = make_float2(acc[mt][j][0], acc[mt][j][1]);
                    if (rB < n)
                        *(float2*)(g_h + (size_t)rB * NCH + col) = make_float2(acc[mt][j][2], acc[mt][j][3]);
                }
            }
        }
    }
}

// ---------------- CSR gather: 4-way software-pipelined ----------------
__global__ void k_gather(const float* __restrict__ bvec, float* __restrict__ out, int n) {
    int node = (blockIdx.x * blockDim.x + threadIdx.x) >> 5;
    int lane = threadIdx.x & 31;
    if (node >= n) return;
    int off = g_rowptr[node];
    int cnt = g_indeg[node];
    float dr = g_dinv[node];
    float inv = dr * dr;
    float4 hv = ((const float4*)(g_h + (size_t)node * NCH))[lane];
    float4 bb = ((const float4*)bvec)[lane];
    float4 acc = make_float4(fmaf(hv.x, inv, bb.x), fmaf(hv.y, inv, bb.y),
                             fmaf(hv.z, inv, bb.z), fmaf(hv.w, inv, bb.w));
    int j = 0;
    for (; j + 4 <= cnt; j += 4) {
        int sa = __ldg(g_esrc + off + j);
        int sb = __ldg(g_esrc + off + j + 1);
        int sc = __ldg(g_esrc + off + j + 2);
        int sd = __ldg(g_esrc + off + j + 3);
        float ca = __ldg(g_dinv + sa) * dr;
        float cb = __ldg(g_dinv + sb) * dr;
        float cc = __ldg(g_dinv + sc) * dr;
        float cd = __ldg(g_dinv + sd) * dr;
        float4 va = __ldg(((const float4*)(g_h + (size_t)sa * NCH)) + lane);
        float4 vb = __ldg(((const float4*)(g_h + (size_t)sb * NCH)) + lane);
        float4 vc = __ldg(((const float4*)(g_h + (size_t)sc * NCH)) + lane);
        float4 vd = __ldg(((const float4*)(g_h + (size_t)sd * NCH)) + lane);
        acc.x = fmaf(va.x, ca, acc.x); acc.y = fmaf(va.y, ca, acc.y);
        acc.z = fmaf(va.z, ca, acc.z); acc.w = fmaf(va.w, ca, acc.w);
        acc.x = fmaf(vb.x, cb, acc.x); acc.y = fmaf(vb.y, cb, acc.y);
        acc.z = fmaf(vb.z, cb, acc.z); acc.w = fmaf(vb.w, cb, acc.w);
        acc.x = fmaf(vc.x, cc, acc.x); acc.y = fmaf(vc.y, cc, acc.y);
        acc.z = fmaf(vc.z, cc, acc.z); acc.w = fmaf(vc.w, cc, acc.w);
        acc.x = fmaf(vd.x, cd, acc.x); acc.y = fmaf(vd.y, cd, acc.y);
        acc.z = fmaf(vd.z, cd, acc.z); acc.w = fmaf(vd.w, cd, acc.w);
    }
    for (; j < cnt; j++) {
        int s = __ldg(g_esrc + off + j);
        float c = __ldg(g_dinv + s) * dr;
        float4 sv = __ldg(((const float4*)(g_h + (size_t)s * NCH)) + lane);
        acc.x = fmaf(sv.x, c, acc.x); acc.y = fmaf(sv.y, c, acc.y);
        acc.z = fmaf(sv.z, c, acc.z); acc.w = fmaf(sv.w, c, acc.w);
    }
    ((float4*)(out + (size_t)node * NCH))[lane] = acc;
}

// ---------------- launch ----------------
extern "C" void kernel_launch(void* const* d_in, const int* in_sizes, int n_in,
                              void* d_out, int out_size) {
    const float* x     = (const float*)d_in[0];
    const int*   ei    = (const int*)  d_in[1];
    const float* a1    = (const float*)d_in[2];
    const float* gamma = (const float*)d_in[3];
    const float* beta  = (const float*)d_in[4];
    const float* W1    = (const float*)d_in[5];
    const float* b1    = (const float*)d_in[6];
    const float* a2    = (const float*)d_in[7];
    const float* W2    = (const float*)d_in[8];
    const float* b2    = (const float*)d_in[9];
    float* out = (float*)d_out;

    int n = in_sizes[0] / NCH;
    int e = in_sizes[1] / 2;
    const int* src = ei;
    const int* dst = ei + e;

    const int SMEM = 6 * 128 * SKB;   // 2 A-buffers (hi+lo) + W (hi+lo) = 208896 B
    cudaFuncSetAttribute(k_mma<0>, cudaFuncAttributeMaxDynamicSharedMemorySize, SMEM);
    cudaFuncSetAttribute(k_mma<1>, cudaFuncAttributeMaxDynamicSharedMemorySize, SMEM);

    float* accPtr = nullptr;
    cudaGetSymbolAddress((void**)&accPtr, g_acc);
    __nv_bfloat16* wtPtr = nullptr;
    cudaGetSymbolAddress((void**)&wtPtr, g_Wt);

    int ntiles = (n + 127) / 128;
    int gatBlocks = (int)(((long long)n * 32 + 255) / 256);

    // 1-3: BN stats path (convW also zeroes CSR counters)
    k_convW<<<(n + 255) / 256, 256>>>(W1, W2, n);
    k_stats<<<1184, 256>>>(x, a1, n);
    k_finalize<<<1, 128>>>(gamma, beta, n);
    // 4: conv1 GEMM (ncu profile slot), warp-specialized persistent
    k_mma<0><<<MMA_GRID, MMA_THREADS, SMEM>>>(x, wtPtr + 0 * NCH * NCH, wtPtr + 1 * NCH * NCH, a1, n, ntiles);
    // CSR build
    k_count<<<(e + 255) / 256, 256>>>(dst, e);
    k_scan1<<<NCHUNK, CHUNK>>>(n);
    k_scan2<<<1, CHUNK>>>();
    k_scan3<<<NCHUNK, CHUNK>>>(n);
    k_fill<<<(e + 255) / 256, 256>>>(src, dst, e);
    // conv1 aggregate
    k_gather<<<gatBlocks, 256>>>(b1, accPtr, n);
    // conv2
    k_mma<1><<<MMA_GRID, MMA_THREADS, SMEM>>>(accPtr, wtPtr + 2 * NCH * NCH, wtPtr + 3 * NCH * NCH, a2, n, ntiles);
    k_gather<<<gatBlocks, 256>>>(b2, out, n);
}